// round 16
// baseline (speedup 1.0000x reference)
#include <cuda_runtime.h>
#include <math.h>

#define BB 64
#define TT 1024
#define II 64
#define HH 512
#define LL 128
#define NCTA 128
#define NTHR 256

// ---------------- smem layout (float offsets) ----------------
#define RSH 652
#define HSB8 (8*RSH)                   /* 5216 */
#define RSX 68
#define XSB8 (8*RSX)                   /* 544 */
#define RSZ 132
#define SCB  (128*37 + 12)             /* 4748: pair-reduced scatter buffer */
#define OFF_HS 0                       /* 4 bufs [phase*2+par] = 20864 */
#define OFF_XS 20864                   /* 4 bufs = 2176 */
#define OFF_ZS 23040                   /* 2112 */
#define OFF_OW 25152                   /* 2 x 520 = 1040 */
#define OFF_OB 26192
#define OFF_B  26208
#define OFF_SC 26272                   /* 4 bufs x 4748 = 18992 -> 45264 */
#define OFF_PDW 45264                  /* prologue overlay [0,32896) is earlier in time */
#define SMEM_FLOATS (OFF_PDW + 48*66 + 16)
#define SMEM_BYTES (SMEM_FLOATS*4)     /* ~194 KB */

typedef unsigned long long ull;

// ---------------- device scratch ----------------
__device__ float g_h[2][BB][HH];
__device__ float g_z[BB][LL];
__device__ float g_M[3*HH*HH];
__device__ float g_cb[3*HH];
__device__ volatile unsigned g_flagF[NCTA*32];
__device__ volatile unsigned g_flagS[8*32*32];

// ---------------- helpers ----------------
__device__ __forceinline__ void ffma2(ull& d, ull a, ull b) {
    asm("fma.rn.f32x2 %0, %1, %2, %0;" : "+l"(d) : "l"(a), "l"(b));
}
__device__ __forceinline__ ull add2(ull a, ull b) {
    ull r; asm("add.rn.f32x2 %0, %1, %2;" : "=l"(r) : "l"(a), "l"(b)); return r;
}
__device__ __forceinline__ ull dup2(float w) {
    ull r; asm("mov.b64 %0, {%1, %1};" : "=l"(r) : "f"(w)); return r;
}
__device__ __forceinline__ float sum2(ull v) {
    return __uint_as_float((unsigned)v) + __uint_as_float((unsigned)(v >> 32));
}
__device__ __forceinline__ float sigm(float x) {
    return __fdividef(1.0f, 1.0f + __expf(-x));
}
__device__ __forceinline__ float tanh_fast(float x) {
    return 1.0f - 2.0f * __fdividef(1.0f, __expf(2.0f * x) + 1.0f);
}
__device__ __forceinline__ unsigned ld_acq(const volatile unsigned* p) {
    unsigned v;
    asm volatile("ld.acquire.gpu.global.u32 %0, [%1];" : "=r"(v) : "l"((const void*)p) : "memory");
    return v;
}
__device__ __forceinline__ void st_rel(volatile unsigned* p, unsigned v) {
    asm volatile("st.release.gpu.global.u32 [%0], %1;" :: "l"((void*)p), "r"(v) : "memory");
}
#define NBAR(id) asm volatile("bar.sync %0, 128;" :: "r"(id) : "memory")

__device__ __forceinline__ void fbar(unsigned target) {
    __syncthreads();
    if (threadIdx.x == 0) { __threadfence(); g_flagF[blockIdx.x * 32] = target; }
    if (threadIdx.x < NCTA) {
        while ((int)(g_flagF[threadIdx.x * 32] - target) < 0) { __nanosleep(64); }
        __threadfence();
    }
    __syncthreads();
}

// per-warp: wait own 4 producers of group g, stage 8 rows x 64 cols
__device__ __forceinline__ void wait_stage8(const float* __restrict__ hsrc, float* hs,
                                            int g, unsigned target) {
    const int w = threadIdx.x >> 5, lane = threadIdx.x & 31;
    const volatile unsigned* fp = g_flagS + (g * 32 + 4 * w + (lane & 3)) * 32;
    while (true) {
        unsigned ok = (lane < 4) ? (unsigned)((int)(ld_acq(fp) - target) >= 0) : 1u;
        if (__all_sync(0xffffffffu, ok)) break;
        __nanosleep(64);
    }
    int row = lane & 7, q4 = lane >> 3;
    const float4* s4 = (const float4*)(hsrc + (g * 8 + row) * HH + 64 * w + 16 * q4);
    float* d = hs + row * RSH + (2 * w + (q4 >> 1)) * 40 + (q4 & 1) * 16;
#pragma unroll
    for (int q = 0; q < 4; q++) *(float4*)(d + 4 * q) = s4[q];
    __syncwarp();
}

__device__ __forceinline__ void load_hs_pad16(float* hs, const float* hsrc, int p) {
    for (int idx = threadIdx.x; idx < 16 * 128; idx += NTHR) {
        int row = idx >> 7, q = idx & 127;
        float4 v = reinterpret_cast<const float4*>(hsrc + (p * 16 + row) * HH)[q];
        *(float4*)(hs + row * RSH + (q >> 3) * 40 + (q & 7) * 4) = v;
    }
}
__device__ __forceinline__ void load_xs8(float* xsm, const float* src, int g) {
    for (int idx = threadIdx.x; idx < 8 * (II / 4); idx += NTHR) {
        int b = idx >> 4, q = idx & 15;
        float4 v = reinterpret_cast<const float4*>(src + (g * 8 + b) * (TT * II))[q];
        *(float4*)(xsm + b * RSX + 4 * q) = v;
    }
}

__device__ __forceinline__ void load_wregs3(
    const float* Whh, const float* Wih, const float* bih, const float* bhh,
    float* sm, int ug,
    ull (&w0)[16], ull (&w1)[16], ull (&w2)[16],
    ull (&x0)[2],  ull (&x1)[2],  ull (&x2)[2])
{
    const int tid = threadIdx.x, u = tid & 15, ks = tid >> 4;
    const int row = ug * 16 + u, k0 = ks * 32;
#pragma unroll
    for (int p = 0; p < 16; p++) {
        w0[p] = *(const ull*)(Whh + (0 * HH + row) * HH + k0 + 2 * p);
        w1[p] = *(const ull*)(Whh + (1 * HH + row) * HH + k0 + 2 * p);
        w2[p] = *(const ull*)(Whh + (2 * HH + row) * HH + k0 + 2 * p);
    }
#pragma unroll
    for (int p = 0; p < 2; p++) {
        x0[p] = *(const ull*)(Wih + (0 * HH + row) * II + ks * 4 + 2 * p);
        x1[p] = *(const ull*)(Wih + (1 * HH + row) * II + ks * 4 + 2 * p);
        x2[p] = *(const ull*)(Wih + (2 * HH + row) * II + ks * 4 + 2 * p);
    }
    if (tid < 16) {
        sm[OFF_B + tid]      = bih[ug * 16 + tid] + bhh[ug * 16 + tid];
        sm[OFF_B + 16 + tid] = bih[HH + ug * 16 + tid] + bhh[HH + ug * 16 + tid];
        sm[OFF_B + 32 + tid] = bih[2 * HH + ug * 16 + tid];
        sm[OFF_B + 48 + tid] = bhh[2 * HH + ug * 16 + tid];
    }
}

__device__ __forceinline__ void load_wregs4(
    const float* Whh, const float* bhh, float* sm, int ug,
    ull (&w0)[16], ull (&w1)[16], ull (&w2)[16], ull (&w3)[16])
{
    const int tid = threadIdx.x, u = tid & 15, ks = tid >> 4;
    const int row = ug * 16 + u, k0 = ks * 32;
#pragma unroll
    for (int p = 0; p < 16; p++) {
        w0[p] = add2(*(const ull*)(Whh + (0 * HH + row) * HH + k0 + 2 * p),
                     *(const ull*)(g_M + (0 * HH + row) * HH + k0 + 2 * p));
        w1[p] = add2(*(const ull*)(Whh + (1 * HH + row) * HH + k0 + 2 * p),
                     *(const ull*)(g_M + (1 * HH + row) * HH + k0 + 2 * p));
        w2[p] = *(const ull*)(Whh + (2 * HH + row) * HH + k0 + 2 * p);
        w3[p] = *(const ull*)(g_M + (2 * HH + row) * HH + k0 + 2 * p);
    }
    if (tid < 16) {
        sm[OFF_B + tid]      = g_cb[ug * 16 + tid] + bhh[ug * 16 + tid];
        sm[OFF_B + 16 + tid] = g_cb[HH + ug * 16 + tid] + bhh[HH + ug * 16 + tid];
        sm[OFF_B + 32 + tid] = g_cb[2 * HH + ug * 16 + tid];
        sm[OFF_B + 48 + tid] = bhh[2 * HH + ug * 16 + tid];
    }
}

// pair-reduce ks-parity (lanes l <-> l^16); lanes<16 write partial w (8 per slot)
__device__ __forceinline__ void pair_scatter(float* scb, int b, int u, int lane, int w,
                                             float s0, float s1, float s2, float s3) {
    s0 += __shfl_xor_sync(0xffffffffu, s0, 16);
    s1 += __shfl_xor_sync(0xffffffffu, s1, 16);
    s2 += __shfl_xor_sync(0xffffffffu, s2, 16);
    s3 += __shfl_xor_sync(0xffffffffu, s3, 16);
    if (lane < 16) {
        float* d = scb + (b * 16 + u) * 37 + w;
        d[0] = s0; d[9] = s1; d[18] = s2; d[27] = s3;
    }
}

__device__ __forceinline__ void gemm3_scatter8(
    const float* hs, const float* xs, float* scb,
    ull (&w0)[16], ull (&w1)[16], ull (&w2)[16],
    ull (&x0)[2],  ull (&x1)[2],  ull (&x2)[2])
{
    const int tid = threadIdx.x, u = tid & 15, ks = tid >> 4;
    const int lane = tid & 31, w = tid >> 5, kof = ks * 40;
    ull a0[8], a1[8], a2[8], a3[8];
#pragma unroll
    for (int j = 0; j < 8; j++) { a0[j] = a1[j] = a2[j] = a3[j] = 0ull; }
#pragma unroll
    for (int p = 0; p < 16; p++) {
        ull wa = w0[p], wb = w1[p], wc = w2[p];
#pragma unroll
        for (int j = 0; j < 8; j++) {
            ull hv = *(const ull*)(hs + j * RSH + kof + 2 * p);
            ffma2(a0[j], hv, wa); ffma2(a1[j], hv, wb); ffma2(a2[j], hv, wc);
        }
    }
#pragma unroll
    for (int p = 0; p < 2; p++) {
        ull wa = x0[p], wb = x1[p], wc = x2[p];
#pragma unroll
        for (int j = 0; j < 8; j++) {
            ull xv = *(const ull*)(xs + j * RSX + ks * 4 + 2 * p);
            ffma2(a0[j], xv, wa); ffma2(a1[j], xv, wb); ffma2(a3[j], xv, wc);
        }
    }
#pragma unroll
    for (int j = 0; j < 8; j++)
        pair_scatter(scb, j, u, lane, w,
                     sum2(a0[j]), sum2(a1[j]), sum2(a2[j]), sum2(a3[j]));
}

__device__ __forceinline__ void gemm4_scatter8(
    const float* hs, float* scb,
    ull (&w0)[16], ull (&w1)[16], ull (&w2)[16], ull (&w3)[16])
{
    const int tid = threadIdx.x, u = tid & 15, ks = tid >> 4;
    const int lane = tid & 31, w = tid >> 5, kof = ks * 40;
    ull a0[8], a1[8], a2[8], a3[8];
#pragma unroll
    for (int j = 0; j < 8; j++) { a0[j] = a1[j] = a2[j] = a3[j] = 0ull; }
#pragma unroll
    for (int p = 0; p < 16; p++) {
        ull wa = w0[p], wb = w1[p], wc = w2[p], wd = w3[p];
#pragma unroll
        for (int j = 0; j < 8; j++) {
            ull hv = *(const ull*)(hs + j * RSH + kof + 2 * p);
            ffma2(a0[j], hv, wa); ffma2(a1[j], hv, wb);
            ffma2(a2[j], hv, wc); ffma2(a3[j], hv, wd);
        }
    }
#pragma unroll
    for (int j = 0; j < 8; j++)
        pair_scatter(scb, j, u, lane, w,
                     sum2(a0[j]), sum2(a1[j]), sum2(a2[j]), sum2(a3[j]));
}

// reduce 8 partials + activations + slice STG; lt in [0,128)
__device__ __forceinline__ void epi8(const float* sm, const float* scb, const float* hs,
                                     float* gdst, int g, int ug, int lt) {
    const int u = lt & 15, b = lt >> 4;
    const float* s = scb + lt * 37;
    float s0 = 0, s1 = 0, s2 = 0, s3 = 0;
#pragma unroll
    for (int q = 0; q < 8; q++) {
        s0 += s[q]; s1 += s[9 + q]; s2 += s[18 + q]; s3 += s[27 + q];
    }
    float r = sigm(s0 + sm[OFF_B + u]);
    float z = sigm(s1 + sm[OFF_B + 16 + u]);
    float n = tanh_fast(s3 + sm[OFF_B + 32 + u] + r * (s2 + sm[OFF_B + 48 + u]));
    const int U = ug * 16 + u;
    float hold = hs[b * RSH + (U >> 5) * 40 + (U & 31)];
    gdst[(g * 8 + b) * HH + U] = (1.0f - z) * n + z * hold;
}

// out[t] slice for group g; lt in [0,128)
__device__ __forceinline__ void outproj8(const float* sm, const float* hs,
                                         float* out, int g, int ug, int t, int lt) {
    int s = lt & 7, il = (lt >> 3) & 1, b = lt >> 4;
    const ull* hrow = (const ull*)(hs + b * RSH);
    const ull* orow = (const ull*)(sm + OFF_OW + il * 520);
    ull acc = 0;
#pragma unroll
    for (int c = 0; c < 16; c++) {
        ffma2(acc, hrow[c * 20 + s],     orow[c * 16 + s]);
        ffma2(acc, hrow[c * 20 + 8 + s], orow[c * 16 + 8 + s]);
    }
    float v = sum2(acc);
    v += __shfl_xor_sync(0xffffffffu, v, 1);
    v += __shfl_xor_sync(0xffffffffu, v, 2);
    v += __shfl_xor_sync(0xffffffffu, v, 4);
    if (s == 0) {
        int ig = ug * 2 + il, bgl = g * 8 + b;
        out[(bgl * TT + t) * II + ig] = v + sm[OFF_OB + il];
    }
}

__global__ void __launch_bounds__(NTHR, 1)
gruvae_kernel(const float* __restrict__ x,    const float* __restrict__ eps,
              const float* __restrict__ eWih, const float* __restrict__ eWhh,
              const float* __restrict__ ebih, const float* __restrict__ ebhh,
              const float* __restrict__ muW,  const float* __restrict__ mub,
              const float* __restrict__ lvW,  const float* __restrict__ lvb,
              const float* __restrict__ l2hW, const float* __restrict__ l2hb,
              const float* __restrict__ dWih, const float* __restrict__ dWhh,
              const float* __restrict__ dbih, const float* __restrict__ dbhh,
              const float* __restrict__ oW,   const float* __restrict__ ob,
              float* __restrict__ out)
{
    extern __shared__ float sm[];
    const int bid = blockIdx.x, ug = bid >> 2, p = bid & 3, tid = threadIdx.x;
    const int gA = 2 * p, gB = 2 * p + 1;
    unsigned gF = g_flagF[bid * 32];
    const unsigned sbA = g_flagS[(gA * 32 + ug) * 32];
    const unsigned sbB = g_flagS[(gB * 32 + ug) * 32];
    volatile unsigned* flA = g_flagS + (gA * 32 + ug) * 32;
    volatile unsigned* flB = g_flagS + (gB * 32 + ug) * 32;

    ull w0[16], w1[16], w2[16], w3[16], x0[2], x1[2], x2[2];

    // ===== prologue: M = dWih @ oW (k-quarter per p), cb =====
    for (int idx = tid; idx < 64 * 512; idx += NTHR) {
        int i = idx >> 9, k = idx & 511;
        sm[i * 514 + k] = oW[i * HH + k];
    }
    for (int idx = tid; idx < 48 * 64; idx += NTHR) {
        int r = idx >> 6, i = idx & 63;
        sm[OFF_PDW + r * 66 + i] = dWih[((r >> 4) * HH + ug * 16 + (r & 15)) * II + i];
    }
    __syncthreads();
    {
        int kp = p * 64 + (tid & 63);
        int rr0 = (tid >> 6) * 12;
        for (int r = rr0; r < rr0 + 12; r++) {
            const float* wrow = sm + OFF_PDW + r * 66;
            ull acc = 0ull;
#pragma unroll 8
            for (int i = 0; i < 64; i++)
                ffma2(acc, dup2(wrow[i]), *(const ull*)(sm + i * 514 + 2 * kp));
            int g = r >> 4, U = ug * 16 + (r & 15);
            *(ull*)(g_M + (g * HH + U) * HH + 2 * kp) = acc;
        }
        if (tid < 48) {
            int g = tid >> 4, m = g * HH + ug * 16 + (tid & 15);
            const float* wrow = sm + OFF_PDW + tid * 66;
            float acc = dbih[m];
            for (int i = 0; i < 64; i++) acc += wrow[i] * ob[i];
            g_cb[m] = acc;
        }
    }
    __syncthreads();

    g_h[0][p * 16 + (tid >> 4)][ug * 16 + (tid & 15)] = 0.0f;
    if (tid == 0) { *flA = sbA + 1; *flB = sbB + 1; }
    load_xs8(sm + OFF_XS + 0 * XSB8, x, gA);
    load_xs8(sm + OFF_XS + 2 * XSB8, x, gB);
    load_wregs3(eWhh, eWih, ebih, ebhh, sm, ug, w0, w1, w2, x0, x1, x2);
    fbar(++gF);

    // ===== encoder: two chains, warp-specialized epilogues =====
    for (int t = 0; t < TT; t++) {
        const int par = t & 1;
        // --- phase A (epi: warps 4-7) ---
        {
            float4 xr; bool pf = (t + 1 < TT) && (tid < 128);
            if (pf) xr = reinterpret_cast<const float4*>(
                x + (t + 1) * II + (gA * 8 + (tid >> 4)) * (TT * II))[tid & 15];
            float* hsb = sm + OFF_HS + (0 * 2 + par) * HSB8;
            float* scb = sm + OFF_SC + (0 * 2 + par) * SCB;
            wait_stage8(&g_h[par][0][0], hsb, gA, sbA + 1 + t);
            gemm3_scatter8(hsb, sm + OFF_XS + (0 * 2 + par) * XSB8, scb,
                           w0, w1, w2, x0, x1, x2);
            if (pf) *(float4*)(sm + OFF_XS + (0 * 2 + (1 - par)) * XSB8
                               + (tid >> 4) * RSX + (tid & 15) * 4) = xr;
            __syncthreads();
            if (tid >= 128) {
                epi8(sm, scb, hsb, &g_h[1 - par][0][0], gA, ug, tid - 128);
                NBAR(1);
                if (tid == 128) st_rel(flA, sbA + 2 + t);
            }
        }
        // --- phase B (epi: warps 0-3) ---
        {
            float4 xr; bool pf = (t + 1 < TT) && (tid < 128);
            if (pf) xr = reinterpret_cast<const float4*>(
                x + (t + 1) * II + (gB * 8 + (tid >> 4)) * (TT * II))[tid & 15];
            float* hsb = sm + OFF_HS + (1 * 2 + par) * HSB8;
            float* scb = sm + OFF_SC + (1 * 2 + par) * SCB;
            wait_stage8(&g_h[par][0][0], hsb, gB, sbB + 1 + t);
            gemm3_scatter8(hsb, sm + OFF_XS + (1 * 2 + par) * XSB8, scb,
                           w0, w1, w2, x0, x1, x2);
            if (pf) *(float4*)(sm + OFF_XS + (1 * 2 + (1 - par)) * XSB8
                               + (tid >> 4) * RSX + (tid & 15) * 4) = xr;
            __syncthreads();
            if (tid < 128) {
                epi8(sm, scb, hsb, &g_h[1 - par][0][0], gB, ug, tid);
                NBAR(2);
                if (tid == 0) st_rel(flB, sbB + 2 + t);
            }
        }
    }

    // ===== latent heads (h_1024 in g_h[0]) =====
    fbar(++gF);
    load_hs_pad16(sm + OFF_HS, &g_h[0][0][0], p);
    __syncthreads();
    const int RECON = BB * TT * II;
    float mu_val = 0.0f;
    if (tid < 128) {
        int b = tid & 15, j = (tid >> 4) & 3, kind = tid >> 6;
        int lat = ug * 4 + j, bglob = p * 16 + b;
        const float4* w4 = (const float4*)((kind ? lvW : muW) + lat * HH);
        const float* hr = sm + OFF_HS + b * RSH;
        float acc = 0.0f;
#pragma unroll
        for (int c = 0; c < 16; c++) {
            const float4* h4 = (const float4*)(hr + c * 40);
#pragma unroll
            for (int qq = 0; qq < 8; qq++) {
                float4 wv = w4[c * 8 + qq], h = h4[qq];
                acc += h.x * wv.x + h.y * wv.y + h.z * wv.z + h.w * wv.w;
            }
        }
        acc += (kind ? lvb : mub)[lat];
        out[RECON + kind * BB * LL + bglob * LL + lat] = acc;
        if (kind) sm[OFF_SC + (tid - 64)] = acc;
        mu_val = acc;
    }
    __syncthreads();
    if (tid < 64) {
        int b = tid & 15, j = tid >> 4;
        int lat = ug * 4 + j, bglob = p * 16 + b;
        g_z[bglob][lat] = mu_val + eps[bglob * LL + lat] * expf(0.5f * sm[OFF_SC + tid]);
    }
    fbar(++gF);

    // ===== h_dec -> g_h[1]; stage decoder state =====
    {
        for (int idx = tid; idx < 16 * (LL / 4); idx += NTHR) {
            int b = idx >> 5, q = idx & 31;
            float4 v = reinterpret_cast<const float4*>(&g_z[p * 16 + b][0])[q];
            *(float4*)(sm + OFF_ZS + b * RSZ + 4 * q) = v;
        }
        __syncthreads();
        int u = tid & 15, b = tid >> 4;
        int U = ug * 16 + u;
        const float4* w4 = (const float4*)(l2hW + U * LL);
        float a0 = 0.0f;
#pragma unroll 4
        for (int q = 0; q < LL / 4; q++) {
            float4 wv = w4[q];
            const float* r0 = sm + OFF_ZS + b * RSZ + 4 * q;
            a0 += r0[0]*wv.x + r0[1]*wv.y + r0[2]*wv.z + r0[3]*wv.w;
        }
        g_h[1][p * 16 + b][U] = a0 + l2hb[U];
    }
    load_wregs3(dWhh, dWih, dbih, dbhh, sm, ug, w0, w1, w2, x0, x1, x2);
    for (int idx = tid; idx < 4 * XSB8; idx += NTHR) sm[OFF_XS + idx] = 0.0f;
    for (int idx = tid; idx < 2 * HH; idx += NTHR)
        sm[OFF_OW + (idx >> 9) * 520 + (idx & 511)] = oW[(ug * 2 + (idx >> 9)) * HH + (idx & 511)];
    if (tid < 2) sm[OFF_OB + tid] = ob[ug * 2 + tid];
    __syncthreads();
    if (tid == 0) { st_rel(flA, sbA + 1026); st_rel(flB, sbB + 1026); }

    // ===== decoder t=0 (plain 3-gate, x=0); full-sync versions =====
    {
        float* hsb = sm + OFF_HS + (0 * 2 + 1) * HSB8;
        float* scb = sm + OFF_SC + (0 * 2 + 1) * SCB;
        wait_stage8(&g_h[1][0][0], hsb, gA, sbA + 1026);
        gemm3_scatter8(hsb, sm + OFF_XS, scb, w0, w1, w2, x0, x1, x2);
        __syncthreads();
        if (tid < 128) epi8(sm, scb, hsb, &g_h[0][0][0], gA, ug, tid);
        __syncthreads();
        if (tid == 0) st_rel(flA, sbA + 1027);
    }
    {
        float* hsb = sm + OFF_HS + (1 * 2 + 1) * HSB8;
        float* scb = sm + OFF_SC + (1 * 2 + 1) * SCB;
        wait_stage8(&g_h[1][0][0], hsb, gB, sbB + 1026);
        gemm3_scatter8(hsb, sm + OFF_XS, scb, w0, w1, w2, x0, x1, x2);
        __syncthreads();
        if (tid < 128) epi8(sm, scb, hsb, &g_h[0][0][0], gB, ug, tid);
        __syncthreads();
        if (tid == 0) st_rel(flB, sbB + 1027);
    }
    load_wregs4(dWhh, dbhh, sm, ug, w0, w1, w2, w3);

    // ===== decoder t=1..1023: warp-specialized epilogues, lagged outproj =====
    for (int t = 1; t < TT; t++) {
        const int par = (t + 1) & 1;               // h_t lives in g_h[par]
        // --- phase A (epi: warps 4-7) ---
        {
            float* hsb = sm + OFF_HS + (0 * 2 + par) * HSB8;
            float* scb = sm + OFF_SC + (0 * 2 + par) * SCB;
            wait_stage8(&g_h[par][0][0], hsb, gA, sbA + 1026 + t);
            gemm4_scatter8(hsb, scb, w0, w1, w2, w3);
            __syncthreads();
            if (tid >= 128) {
                epi8(sm, scb, hsb, &g_h[1 - par][0][0], gA, ug, tid - 128);
                NBAR(1);
                if (tid == 128) st_rel(flA, sbA + 1027 + t);
                outproj8(sm, hsb, out, gA, ug, t - 1, tid - 128);
            }
        }
        // --- phase B (epi: warps 0-3) ---
        {
            float* hsb = sm + OFF_HS + (1 * 2 + par) * HSB8;
            float* scb = sm + OFF_SC + (1 * 2 + par) * SCB;
            wait_stage8(&g_h[par][0][0], hsb, gB, sbB + 1026 + t);
            gemm4_scatter8(hsb, scb, w0, w1, w2, w3);
            __syncthreads();
            if (tid < 128) {
                epi8(sm, scb, hsb, &g_h[1 - par][0][0], gB, ug, tid);
                NBAR(2);
                if (tid == 0) st_rel(flB, sbB + 1027 + t);
                outproj8(sm, hsb, out, gB, ug, t - 1, tid);
            }
        }
    }

    // ===== tail: out[1023] from h_1024 (in g_h[1]) =====
    {
        float* hsb = sm + OFF_HS + (0 * 2 + 1) * HSB8;
        wait_stage8(&g_h[1][0][0], hsb, gA, sbA + 2050);
        __syncthreads();
        if (tid < 128) outproj8(sm, hsb, out, gA, ug, TT - 1, tid);
    }
    {
        float* hsb = sm + OFF_HS + (1 * 2 + 1) * HSB8;
        wait_stage8(&g_h[1][0][0], hsb, gB, sbB + 2050);
        __syncthreads();
        if (tid < 128) outproj8(sm, hsb, out, gB, ug, TT - 1, tid);
    }
}

extern "C" void kernel_launch(void* const* d_in, const int* in_sizes, int n_in,
                              void* d_out, int out_size) {
    (void)in_sizes; (void)n_in; (void)out_size;
    cudaFuncSetAttribute(gruvae_kernel,
                         cudaFuncAttributeMaxDynamicSharedMemorySize, SMEM_BYTES);
    gruvae_kernel<<<NCTA, NTHR, SMEM_BYTES>>>(
        (const float*)d_in[0],  (const float*)d_in[1],
        (const float*)d_in[2],  (const float*)d_in[3],
        (const float*)d_in[4],  (const float*)d_in[5],
        (const float*)d_in[6],  (const float*)d_in[7],
        (const float*)d_in[8],  (const float*)d_in[9],
        (const float*)d_in[10], (const float*)d_in[11],
        (const float*)d_in[12], (const float*)d_in[13],
        (const float*)d_in[14], (const float*)d_in[15],
        (const float*)d_in[16], (const float*)d_in[17],
        (float*)d_out);
}

// round 17
// speedup vs baseline: 1.0210x; 1.0210x over previous
#include <cuda_runtime.h>
#include <math.h>

#define BB 64
#define TT 1024
#define II 64
#define HH 512
#define LL 128
#define NCTA 128
#define NTHR 256

// ---------------- smem layout (float offsets) ----------------
#define RSH 652
#define HSB8 (8*RSH)                   /* 5216 */
#define RSX 68
#define XSB8 (8*RSX)                   /* 544 */
#define RSZ 132
#define OFF_HS 0                       /* 4 bufs [phase*2+par] = 20864 */
#define OFF_XS (4*HSB8)                /* 4 bufs = 2176 */
#define OFF_ZS (OFF_XS + 4*XSB8)      /* 23040 */
#define OFF_OW 25152                   /* 2 x 520 */
#define OFF_OB 26192
#define OFF_B  26208
#define OFF_SC 26272                   /* 128 slots x 69 + 32 */
#define OFF_PDW 35136
#define SMEM_FLOATS (OFF_PDW + 48*66 + 16)
#define SMEM_BYTES (SMEM_FLOATS*4)     /* ~153 KB */

typedef unsigned long long ull;

// ---------------- device scratch ----------------
__device__ float g_h[2][BB][HH];
__device__ float g_z[BB][LL];
__device__ float g_M[3*HH*HH];
__device__ float g_cb[3*HH];
__device__ volatile unsigned g_flagF[NCTA*32];
__device__ volatile unsigned g_flagS[8*32*32];

// ---------------- helpers ----------------
__device__ __forceinline__ void ffma2(ull& d, ull a, ull b) {
    asm("fma.rn.f32x2 %0, %1, %2, %0;" : "+l"(d) : "l"(a), "l"(b));
}
__device__ __forceinline__ ull add2(ull a, ull b) {
    ull r; asm("add.rn.f32x2 %0, %1, %2;" : "=l"(r) : "l"(a), "l"(b)); return r;
}
__device__ __forceinline__ ull dup2(float w) {
    ull r; asm("mov.b64 %0, {%1, %1};" : "=l"(r) : "f"(w)); return r;
}
__device__ __forceinline__ float sum2(ull v) {
    return __uint_as_float((unsigned)v) + __uint_as_float((unsigned)(v >> 32));
}
__device__ __forceinline__ float sigm(float x) {
    return __fdividef(1.0f, 1.0f + __expf(-x));
}
__device__ __forceinline__ float tanh_fast(float x) {
    return 1.0f - 2.0f * __fdividef(1.0f, __expf(2.0f * x) + 1.0f);
}
__device__ __forceinline__ unsigned ld_acq(const volatile unsigned* p) {
    unsigned v;
    asm volatile("ld.acquire.gpu.global.u32 %0, [%1];" : "=r"(v) : "l"((const void*)p) : "memory");
    return v;
}
__device__ __forceinline__ void st_rel(volatile unsigned* p, unsigned v) {
    asm volatile("st.release.gpu.global.u32 [%0], %1;" :: "l"((void*)p), "r"(v) : "memory");
}

__device__ __forceinline__ void fbar(unsigned target) {
    __syncthreads();
    if (threadIdx.x == 0) { __threadfence(); g_flagF[blockIdx.x * 32] = target; }
    if (threadIdx.x < NCTA) {
        while ((int)(g_flagF[threadIdx.x * 32] - target) < 0) { __nanosleep(64); }
        __threadfence();
    }
    __syncthreads();
}

// per-warp incremental stage: lane quarter q waits ONLY its producer (4w+q)
// and stages that producer's 16-col slice immediately; __syncwarp joins.
__device__ __forceinline__ void wait_stage8(const float* __restrict__ hsrc, float* hs,
                                            int g, unsigned target) {
    const int w = threadIdx.x >> 5, lane = threadIdx.x & 31;
    const int q = lane >> 3, row = lane & 7;
    const volatile unsigned* fp = g_flagS + (g * 32 + 4 * w + q) * 32;
    while ((int)(ld_acq(fp) - target) < 0) { __nanosleep(64); }
    const float4* s4 = (const float4*)(hsrc + (g * 8 + row) * HH + 64 * w + 16 * q);
    float* d = hs + row * RSH + (2 * w + (q >> 1)) * 40 + (q & 1) * 16;
#pragma unroll
    for (int qq = 0; qq < 4; qq++) *(float4*)(d + 4 * qq) = s4[qq];
    __syncwarp();
}

__device__ __forceinline__ void load_hs_pad16(float* hs, const float* hsrc, int p) {
    for (int idx = threadIdx.x; idx < 16 * 128; idx += NTHR) {
        int row = idx >> 7, q = idx & 127;
        float4 v = reinterpret_cast<const float4*>(hsrc + (p * 16 + row) * HH)[q];
        *(float4*)(hs + row * RSH + (q >> 3) * 40 + (q & 7) * 4) = v;
    }
}
__device__ __forceinline__ void load_xs8(float* xsm, const float* src, int g) {
    for (int idx = threadIdx.x; idx < 8 * (II / 4); idx += NTHR) {
        int b = idx >> 4, q = idx & 15;
        float4 v = reinterpret_cast<const float4*>(src + (g * 8 + b) * (TT * II))[q];
        *(float4*)(xsm + b * RSX + 4 * q) = v;
    }
}

__device__ __forceinline__ void load_wregs3(
    const float* Whh, const float* Wih, const float* bih, const float* bhh,
    float* sm, int ug,
    ull (&w0)[16], ull (&w1)[16], ull (&w2)[16],
    ull (&x0)[2],  ull (&x1)[2],  ull (&x2)[2])
{
    const int tid = threadIdx.x, u = tid & 15, ks = tid >> 4;
    const int row = ug * 16 + u, k0 = ks * 32;
#pragma unroll
    for (int p = 0; p < 16; p++) {
        w0[p] = *(const ull*)(Whh + (0 * HH + row) * HH + k0 + 2 * p);
        w1[p] = *(const ull*)(Whh + (1 * HH + row) * HH + k0 + 2 * p);
        w2[p] = *(const ull*)(Whh + (2 * HH + row) * HH + k0 + 2 * p);
    }
#pragma unroll
    for (int p = 0; p < 2; p++) {
        x0[p] = *(const ull*)(Wih + (0 * HH + row) * II + ks * 4 + 2 * p);
        x1[p] = *(const ull*)(Wih + (1 * HH + row) * II + ks * 4 + 2 * p);
        x2[p] = *(const ull*)(Wih + (2 * HH + row) * II + ks * 4 + 2 * p);
    }
    if (tid < 16) {
        sm[OFF_B + tid]      = bih[ug * 16 + tid] + bhh[ug * 16 + tid];
        sm[OFF_B + 16 + tid] = bih[HH + ug * 16 + tid] + bhh[HH + ug * 16 + tid];
        sm[OFF_B + 32 + tid] = bih[2 * HH + ug * 16 + tid];
        sm[OFF_B + 48 + tid] = bhh[2 * HH + ug * 16 + tid];
    }
}

__device__ __forceinline__ void load_wregs4(
    const float* Whh, const float* bhh, float* sm, int ug,
    ull (&w0)[16], ull (&w1)[16], ull (&w2)[16], ull (&w3)[16])
{
    const int tid = threadIdx.x, u = tid & 15, ks = tid >> 4;
    const int row = ug * 16 + u, k0 = ks * 32;
#pragma unroll
    for (int p = 0; p < 16; p++) {
        w0[p] = add2(*(const ull*)(Whh + (0 * HH + row) * HH + k0 + 2 * p),
                     *(const ull*)(g_M + (0 * HH + row) * HH + k0 + 2 * p));
        w1[p] = add2(*(const ull*)(Whh + (1 * HH + row) * HH + k0 + 2 * p),
                     *(const ull*)(g_M + (1 * HH + row) * HH + k0 + 2 * p));
        w2[p] = *(const ull*)(Whh + (2 * HH + row) * HH + k0 + 2 * p);
        w3[p] = *(const ull*)(g_M + (2 * HH + row) * HH + k0 + 2 * p);
    }
    if (tid < 16) {
        sm[OFF_B + tid]      = g_cb[ug * 16 + tid] + bhh[ug * 16 + tid];
        sm[OFF_B + 16 + tid] = g_cb[HH + ug * 16 + tid] + bhh[HH + ug * 16 + tid];
        sm[OFF_B + 32 + tid] = g_cb[2 * HH + ug * 16 + tid];
        sm[OFF_B + 48 + tid] = bhh[2 * HH + ug * 16 + tid];
    }
}

__device__ __forceinline__ void gemm3_scatter8(
    const float* hs, const float* xs, float* sm,
    ull (&w0)[16], ull (&w1)[16], ull (&w2)[16],
    ull (&x0)[2],  ull (&x1)[2],  ull (&x2)[2])
{
    const int tid = threadIdx.x, u = tid & 15, ks = tid >> 4, kof = ks * 40;
    ull a0[8], a1[8], a2[8], a3[8];
#pragma unroll
    for (int j = 0; j < 8; j++) { a0[j] = a1[j] = a2[j] = a3[j] = 0ull; }
#pragma unroll
    for (int p = 0; p < 16; p++) {
        ull wa = w0[p], wb = w1[p], wc = w2[p];
#pragma unroll
        for (int j = 0; j < 8; j++) {
            ull hv = *(const ull*)(hs + j * RSH + kof + 2 * p);
            ffma2(a0[j], hv, wa); ffma2(a1[j], hv, wb); ffma2(a2[j], hv, wc);
        }
    }
#pragma unroll
    for (int p = 0; p < 2; p++) {
        ull wa = x0[p], wb = x1[p], wc = x2[p];
#pragma unroll
        for (int j = 0; j < 8; j++) {
            ull xv = *(const ull*)(xs + j * RSX + ks * 4 + 2 * p);
            ffma2(a0[j], xv, wa); ffma2(a1[j], xv, wb); ffma2(a3[j], xv, wc);
        }
    }
#pragma unroll
    for (int j = 0; j < 8; j++) {
        float* d = sm + OFF_SC + (j * 16 + u) * 69 + ks;
        d[0] = sum2(a0[j]); d[17] = sum2(a1[j]);
        d[34] = sum2(a2[j]); d[51] = sum2(a3[j]);
    }
}

__device__ __forceinline__ void gemm4_scatter8(
    const float* hs, float* sm,
    ull (&w0)[16], ull (&w1)[16], ull (&w2)[16], ull (&w3)[16])
{
    const int tid = threadIdx.x, u = tid & 15, ks = tid >> 4, kof = ks * 40;
    ull a0[8], a1[8], a2[8], a3[8];
#pragma unroll
    for (int j = 0; j < 8; j++) { a0[j] = a1[j] = a2[j] = a3[j] = 0ull; }
#pragma unroll
    for (int p = 0; p < 16; p++) {
        ull wa = w0[p], wb = w1[p], wc = w2[p], wd = w3[p];
#pragma unroll
        for (int j = 0; j < 8; j++) {
            ull hv = *(const ull*)(hs + j * RSH + kof + 2 * p);
            ffma2(a0[j], hv, wa); ffma2(a1[j], hv, wb);
            ffma2(a2[j], hv, wc); ffma2(a3[j], hv, wd);
        }
    }
#pragma unroll
    for (int j = 0; j < 8; j++) {
        float* d = sm + OFF_SC + (j * 16 + u) * 69 + ks;
        d[0] = sum2(a0[j]); d[17] = sum2(a1[j]);
        d[34] = sum2(a2[j]); d[51] = sum2(a3[j]);
    }
}

__device__ __forceinline__ void epilogue8(float* sm, const float* hs, float* gdst,
                                          int g, int ug) {
    const int tid = threadIdx.x;
    if (tid < 128) {
        const int u = tid & 15, b = tid >> 4;
        const float* s = sm + OFF_SC + tid * 69;
        float s0 = 0, s1 = 0, s2 = 0, s3 = 0;
#pragma unroll
        for (int q = 0; q < 16; q++) {
            s0 += s[q]; s1 += s[17 + q]; s2 += s[34 + q]; s3 += s[51 + q];
        }
        float r = sigm(s0 + sm[OFF_B + u]);
        float z = sigm(s1 + sm[OFF_B + 16 + u]);
        float n = tanh_fast(s3 + sm[OFF_B + 32 + u] + r * (s2 + sm[OFF_B + 48 + u]));
        const int U = ug * 16 + u;
        float hold = hs[b * RSH + (U >> 5) * 40 + (U & 31)];
        gdst[(g * 8 + b) * HH + U] = (1.0f - z) * n + z * hold;
    }
}

__device__ __forceinline__ void outproj8(const float* sm, const float* hs,
                                         float* out, int g, int ug, int t) {
    const int tid = threadIdx.x;
    if (tid < 128) {
        int s = tid & 7, il = (tid >> 3) & 1, b = tid >> 4;
        const ull* hrow = (const ull*)(hs + b * RSH);
        const ull* orow = (const ull*)(sm + OFF_OW + il * 520);
        ull acc = 0;
#pragma unroll
        for (int c = 0; c < 16; c++) {
            ffma2(acc, hrow[c * 20 + s],     orow[c * 16 + s]);
            ffma2(acc, hrow[c * 20 + 8 + s], orow[c * 16 + 8 + s]);
        }
        float v = sum2(acc);
        v += __shfl_xor_sync(0xffffffffu, v, 1);
        v += __shfl_xor_sync(0xffffffffu, v, 2);
        v += __shfl_xor_sync(0xffffffffu, v, 4);
        if (s == 0) {
            int ig = ug * 2 + il, bgl = g * 8 + b;
            out[(bgl * TT + t) * II + ig] = v + sm[OFF_OB + il];
        }
    }
}

__global__ void __launch_bounds__(NTHR, 1)
gruvae_kernel(const float* __restrict__ x,    const float* __restrict__ eps,
              const float* __restrict__ eWih, const float* __restrict__ eWhh,
              const float* __restrict__ ebih, const float* __restrict__ ebhh,
              const float* __restrict__ muW,  const float* __restrict__ mub,
              const float* __restrict__ lvW,  const float* __restrict__ lvb,
              const float* __restrict__ l2hW, const float* __restrict__ l2hb,
              const float* __restrict__ dWih, const float* __restrict__ dWhh,
              const float* __restrict__ dbih, const float* __restrict__ dbhh,
              const float* __restrict__ oW,   const float* __restrict__ ob,
              float* __restrict__ out)
{
    extern __shared__ float sm[];
    const int bid = blockIdx.x, ug = bid >> 2, p = bid & 3, tid = threadIdx.x;
    const int gA = 2 * p, gB = 2 * p + 1;
    unsigned gF = g_flagF[bid * 32];
    const unsigned sbA = g_flagS[(gA * 32 + ug) * 32];
    const unsigned sbB = g_flagS[(gB * 32 + ug) * 32];
    volatile unsigned* flA = g_flagS + (gA * 32 + ug) * 32;
    volatile unsigned* flB = g_flagS + (gB * 32 + ug) * 32;

    ull w0[16], w1[16], w2[16], w3[16], x0[2], x1[2], x2[2];

    // ===== prologue: M = dWih @ oW (k-quarter per p), cb =====
    for (int idx = tid; idx < 64 * 512; idx += NTHR) {
        int i = idx >> 9, k = idx & 511;
        sm[i * 514 + k] = oW[i * HH + k];
    }
    for (int idx = tid; idx < 48 * 64; idx += NTHR) {
        int r = idx >> 6, i = idx & 63;
        sm[OFF_PDW + r * 66 + i] = dWih[((r >> 4) * HH + ug * 16 + (r & 15)) * II + i];
    }
    __syncthreads();
    {
        int kp = p * 64 + (tid & 63);
        int rr0 = (tid >> 6) * 12;
        for (int r = rr0; r < rr0 + 12; r++) {
            const float* wrow = sm + OFF_PDW + r * 66;
            ull acc = 0ull;
#pragma unroll 8
            for (int i = 0; i < 64; i++)
                ffma2(acc, dup2(wrow[i]), *(const ull*)(sm + i * 514 + 2 * kp));
            int g = r >> 4, U = ug * 16 + (r & 15);
            *(ull*)(g_M + (g * HH + U) * HH + 2 * kp) = acc;
        }
        if (tid < 48) {
            int g = tid >> 4, m = g * HH + ug * 16 + (tid & 15);
            const float* wrow = sm + OFF_PDW + tid * 66;
            float acc = dbih[m];
            for (int i = 0; i < 64; i++) acc += wrow[i] * ob[i];
            g_cb[m] = acc;
        }
    }
    __syncthreads();

    g_h[0][p * 16 + (tid >> 4)][ug * 16 + (tid & 15)] = 0.0f;
    if (tid == 0) { *flA = sbA + 1; *flB = sbB + 1; }
    load_xs8(sm + OFF_XS + 0 * XSB8, x, gA);
    load_xs8(sm + OFF_XS + 2 * XSB8, x, gB);
    load_wregs3(eWhh, eWih, ebih, ebhh, sm, ug, w0, w1, w2, x0, x1, x2);
    fbar(++gF);

    // ===== encoder: two interleaved dataflow chains =====
    for (int t = 0; t < TT; t++) {
        const int par = t & 1;
        {
            float* hsb = sm + OFF_HS + (0 * 2 + par) * HSB8;
            float* xsb = sm + OFF_XS + (0 * 2 + par) * XSB8;
            wait_stage8(&g_h[par][0][0], hsb, gA, sbA + 1 + t);
            gemm3_scatter8(hsb, xsb, sm, w0, w1, w2, x0, x1, x2);
            if (t + 1 < TT)
                load_xs8(sm + OFF_XS + (0 * 2 + (1 - par)) * XSB8, x + (t + 1) * II, gA);
            __syncthreads();
            epilogue8(sm, hsb, &g_h[1 - par][0][0], gA, ug);
            __syncthreads();
            if (tid == 0) st_rel(flA, sbA + 2 + t);
        }
        {
            float* hsb = sm + OFF_HS + (1 * 2 + par) * HSB8;
            float* xsb = sm + OFF_XS + (1 * 2 + par) * XSB8;
            wait_stage8(&g_h[par][0][0], hsb, gB, sbB + 1 + t);
            gemm3_scatter8(hsb, xsb, sm, w0, w1, w2, x0, x1, x2);
            if (t + 1 < TT)
                load_xs8(sm + OFF_XS + (1 * 2 + (1 - par)) * XSB8, x + (t + 1) * II, gB);
            __syncthreads();
            epilogue8(sm, hsb, &g_h[1 - par][0][0], gB, ug);
            __syncthreads();
            if (tid == 0) st_rel(flB, sbB + 2 + t);
        }
    }

    // ===== latent heads (h_1024 in g_h[0]) =====
    fbar(++gF);
    load_hs_pad16(sm + OFF_HS, &g_h[0][0][0], p);
    __syncthreads();
    const int RECON = BB * TT * II;
    float mu_val = 0.0f;
    if (tid < 128) {
        int b = tid & 15, j = (tid >> 4) & 3, kind = tid >> 6;
        int lat = ug * 4 + j, bglob = p * 16 + b;
        const float4* w4 = (const float4*)((kind ? lvW : muW) + lat * HH);
        const float* hr = sm + OFF_HS + b * RSH;
        float acc = 0.0f;
#pragma unroll
        for (int c = 0; c < 16; c++) {
            const float4* h4 = (const float4*)(hr + c * 40);
#pragma unroll
            for (int qq = 0; qq < 8; qq++) {
                float4 wv = w4[c * 8 + qq], h = h4[qq];
                acc += h.x * wv.x + h.y * wv.y + h.z * wv.z + h.w * wv.w;
            }
        }
        acc += (kind ? lvb : mub)[lat];
        out[RECON + kind * BB * LL + bglob * LL + lat] = acc;
        if (kind) sm[OFF_SC + (tid - 64)] = acc;
        mu_val = acc;
    }
    __syncthreads();
    if (tid < 64) {
        int b = tid & 15, j = tid >> 4;
        int lat = ug * 4 + j, bglob = p * 16 + b;
        g_z[bglob][lat] = mu_val + eps[bglob * LL + lat] * expf(0.5f * sm[OFF_SC + tid]);
    }
    fbar(++gF);

    // ===== h_dec -> g_h[1]; stage decoder state =====
    {
        for (int idx = tid; idx < 16 * (LL / 4); idx += NTHR) {
            int b = idx >> 5, q = idx & 31;
            float4 v = reinterpret_cast<const float4*>(&g_z[p * 16 + b][0])[q];
            *(float4*)(sm + OFF_ZS + b * RSZ + 4 * q) = v;
        }
        __syncthreads();
        int u = tid & 15, b = tid >> 4;
        int U = ug * 16 + u;
        const float4* w4 = (const float4*)(l2hW + U * LL);
        float a0 = 0.0f;
#pragma unroll 4
        for (int q = 0; q < LL / 4; q++) {
            float4 wv = w4[q];
            const float* r0 = sm + OFF_ZS + b * RSZ + 4 * q;
            a0 += r0[0]*wv.x + r0[1]*wv.y + r0[2]*wv.z + r0[3]*wv.w;
        }
        g_h[1][p * 16 + b][U] = a0 + l2hb[U];
    }
    load_wregs3(dWhh, dWih, dbih, dbhh, sm, ug, w0, w1, w2, x0, x1, x2);
    for (int idx = tid; idx < 4 * XSB8; idx += NTHR) sm[OFF_XS + idx] = 0.0f;
    for (int idx = tid; idx < 2 * HH; idx += NTHR)
        sm[OFF_OW + (idx >> 9) * 520 + (idx & 511)] = oW[(ug * 2 + (idx >> 9)) * HH + (idx & 511)];
    if (tid < 2) sm[OFF_OB + tid] = ob[ug * 2 + tid];
    __syncthreads();
    if (tid == 0) { st_rel(flA, sbA + 1026); st_rel(flB, sbB + 1026); }

    // ===== decoder t=0 (plain 3-gate, x=0); h_dec in g_h[1] =====
    {
        float* hsb = sm + OFF_HS + (0 * 2 + 1) * HSB8;
        wait_stage8(&g_h[1][0][0], hsb, gA, sbA + 1026);
        gemm3_scatter8(hsb, sm + OFF_XS, sm, w0, w1, w2, x0, x1, x2);
        __syncthreads();
        epilogue8(sm, hsb, &g_h[0][0][0], gA, ug);
        __syncthreads();
        if (tid == 0) st_rel(flA, sbA + 1027);
    }
    {
        float* hsb = sm + OFF_HS + (1 * 2 + 1) * HSB8;
        wait_stage8(&g_h[1][0][0], hsb, gB, sbB + 1026);
        gemm3_scatter8(hsb, sm + OFF_XS, sm, w0, w1, w2, x0, x1, x2);
        __syncthreads();
        epilogue8(sm, hsb, &g_h[0][0][0], gB, ug);
        __syncthreads();
        if (tid == 0) st_rel(flB, sbB + 1027);
    }
    load_wregs4(dWhh, dbhh, sm, ug, w0, w1, w2, w3);

    // ===== decoder t=1..1023: merged weights, interleaved, lagged outproj =====
    for (int t = 1; t < TT; t++) {
        const int par = (t + 1) & 1;
        {
            float* hsb = sm + OFF_HS + (0 * 2 + par) * HSB8;
            wait_stage8(&g_h[par][0][0], hsb, gA, sbA + 1026 + t);
            gemm4_scatter8(hsb, sm, w0, w1, w2, w3);
            __syncthreads();
            epilogue8(sm, hsb, &g_h[1 - par][0][0], gA, ug);
            __syncthreads();
            if (tid == 0) st_rel(flA, sbA + 1027 + t);
            outproj8(sm, hsb, out, gA, ug, t - 1);
        }
        {
            float* hsb = sm + OFF_HS + (1 * 2 + par) * HSB8;
            wait_stage8(&g_h[par][0][0], hsb, gB, sbB + 1026 + t);
            gemm4_scatter8(hsb, sm, w0, w1, w2, w3);
            __syncthreads();
            epilogue8(sm, hsb, &g_h[1 - par][0][0], gB, ug);
            __syncthreads();
            if (tid == 0) st_rel(flB, sbB + 1027 + t);
            outproj8(sm, hsb, out, gB, ug, t - 1);
        }
    }

    // ===== tail: out[1023] from h_1024 (in g_h[1]) =====
    {
        float* hsb = sm + OFF_HS + (0 * 2 + 1) * HSB8;
        wait_stage8(&g_h[1][0][0], hsb, gA, sbA + 2050);
        __syncthreads();
        outproj8(sm, hsb, out, gA, ug, TT - 1);
    }
    {
        float* hsb = sm + OFF_HS + (1 * 2 + 1) * HSB8;
        wait_stage8(&g_h[1][0][0], hsb, gB, sbB + 2050);
        __syncthreads();
        outproj8(sm, hsb, out, gB, ug, TT - 1);
    }
}

extern "C" void kernel_launch(void* const* d_in, const int* in_sizes, int n_in,
                              void* d_out, int out_size) {
    (void)in_sizes; (void)n_in; (void)out_size;
    cudaFuncSetAttribute(gruvae_kernel,
                         cudaFuncAttributeMaxDynamicSharedMemorySize, SMEM_BYTES);
    gruvae_kernel<<<NCTA, NTHR, SMEM_BYTES>>>(
        (const float*)d_in[0],  (const float*)d_in[1],
        (const float*)d_in[2],  (const float*)d_in[3],
        (const float*)d_in[4],  (const float*)d_in[5],
        (const float*)d_in[6],  (const float*)d_in[7],
        (const float*)d_in[8],  (const float*)d_in[9],
        (const float*)d_in[10], (const float*)d_in[11],
        (const float*)d_in[12], (const float*)d_in[13],
        (const float*)d_in[14], (const float*)d_in[15],
        (const float*)d_in[16], (const float*)d_in[17],
        (float*)d_out);
}